// round 2
// baseline (speedup 1.0000x reference)
#include <cuda_runtime.h>
#include <stdint.h>

// Problem constants (fixed by the dataset)
#define B_  4
#define L_  5
#define C_  256
#define H_  100
#define W_  252
#define HW_ (H_ * W_)          // 25200
#define KSEL 1024
#define NBL (B_ * L_)          // 20
#define NWORDS 788             // ceil(25200/32)

// Per-(b,l) pixel bitmask: bit = pixel survives top-K threshold.
__device__ uint32_t g_bitmask[NBL][800];

// Monotone map: float -> uint32 preserving order (ascending).
__device__ __forceinline__ uint32_t f2u(float f) {
    uint32_t u = __float_as_uint(f);
    return (u & 0x80000000u) ? ~u : (u | 0x80000000u);
}

// ---------------------------------------------------------------------------
// Kernel 1: per (b, l>0), exact K-th-largest radix select over
// d[hw] = max_c (psm[b,l,c,hw] - psm[b,0,c,hw]), then write pixel bitmask.
// One block per (b,l). 16 blocks total; tiny kernel (~6.4 MB traffic).
// ---------------------------------------------------------------------------
__global__ __launch_bounds__(1024, 1) void select_kernel(const float* __restrict__ psm) {
    const int blk = blockIdx.x;          // 0..15
    const int b = blk >> 2;
    const int l = 1 + (blk & 3);
    const int bl = b * L_ + l;

    const float* __restrict__ p_l = psm + (size_t)bl * 2 * HW_;
    const float* __restrict__ p_0 = psm + (size_t)(b * L_) * 2 * HW_;

    const int tid = threadIdx.x;

    // Each thread keeps its strided slice of keys in a local array.
    uint32_t keys[25];
    int nk = 0;
    for (int hw = tid; hw < HW_; hw += 1024) {
        float d0 = p_l[hw]        - p_0[hw];
        float d1 = p_l[HW_ + hw]  - p_0[HW_ + hw];
        keys[nk++] = f2u(fmaxf(d0, d1));
    }

    __shared__ uint32_t hist[256];
    __shared__ uint32_t s_prefix, s_rem;
    if (tid == 0) { s_prefix = 0u; s_rem = KSEL; }

    // 4 MSB-first radix passes (8 bits each) -> exact key of K-th largest.
    for (int shift = 24; shift >= 0; shift -= 8) {
        if (tid < 256) hist[tid] = 0u;
        __syncthreads();

        const uint32_t prefix = s_prefix;
        const uint32_t pmask = (shift == 24) ? 0u : (0xFFFFFFFFu << (shift + 8));
        for (int i = 0; i < nk; i++) {
            uint32_t k = keys[i];
            if ((k & pmask) == (prefix & pmask))
                atomicAdd(&hist[(k >> shift) & 255u], 1u);
        }
        __syncthreads();

        if (tid == 0) {
            uint32_t rem = s_rem;
            uint32_t cum = 0;
            int d = 255;
            for (; d >= 0; d--) {
                if (cum + hist[d] >= rem) break;
                cum += hist[d];
            }
            if (d < 0) d = 0;  // safety; invariant guarantees d >= 0
            s_rem = rem - cum;
            s_prefix = prefix | ((uint32_t)d << shift);
        }
        __syncthreads();
    }

    const uint32_t T = s_prefix;   // exact key of rank-K element

    // Build bitmask in shared, then flush to global.
    __shared__ uint32_t words[800];
    for (int w = tid; w < NWORDS; w += 1024) words[w] = 0u;
    __syncthreads();
    {
        int i = 0;
        for (int hw = tid; hw < HW_; hw += 1024, i++) {
            if (keys[i] >= T) atomicOr(&words[hw >> 5], 1u << (hw & 31));
        }
    }
    __syncthreads();
    for (int w = tid; w < NWORDS; w += 1024) g_bitmask[bl][w] = words[w];
}

// ---------------------------------------------------------------------------
// Kernel 2: stream x -> out. Pure bandwidth.
//   l==0              : copy
//   l>0 && mask==0    : write zeros (NO x read)
//   l>0 && mask!=0    : x * bit(pixel)
// One float4 per thread. grid = (6300, 1, 20), block = 256.
// Per slice: C*HW/4 = 1,612,800 float4 = 6300 blocks * 256 threads.
// ---------------------------------------------------------------------------
__global__ __launch_bounds__(256) void apply_kernel(const float* __restrict__ x,
                                                    const int* __restrict__ mask,
                                                    float* __restrict__ out) {
    const int bl = blockIdx.z;           // 0..19
    const int l = bl % L_;
    const size_t slice = (size_t)bl * (size_t)(C_ * HW_);
    const int idx4 = blockIdx.x * 256 + threadIdx.x;   // 0..1,612,799
    const size_t off = slice + (size_t)idx4 * 4;

    float4* __restrict__ o4 = reinterpret_cast<float4*>(out + off);

    if (l == 0) {
        *o4 = *reinterpret_cast<const float4*>(x + off);
        return;
    }
    if (mask[bl] == 0) {
        *o4 = make_float4(0.f, 0.f, 0.f, 0.f);
        return;
    }

    float4 v = *reinterpret_cast<const float4*>(x + off);
    // pixel index of first lane element within the (b,l) slice
    const int hw = (idx4 % (HW_ / 4)) * 4;     // HW_/4 = 6300; hw % 4 == 0
    const uint32_t wbits = g_bitmask[bl][hw >> 5] >> (hw & 31);
    v.x = (wbits & 1u) ? v.x : 0.f;
    v.y = (wbits & 2u) ? v.y : 0.f;
    v.z = (wbits & 4u) ? v.z : 0.f;
    v.w = (wbits & 8u) ? v.w : 0.f;
    *o4 = v;
}

extern "C" void kernel_launch(void* const* d_in, const int* in_sizes, int n_in,
                              void* d_out, int out_size) {
    const float* x   = (const float*)d_in[0];
    const float* psm = (const float*)d_in[1];
    const int*  mask = (const int*)d_in[2];
    float* out = (float*)d_out;

    select_kernel<<<B_ * (L_ - 1), 1024>>>(psm);

    dim3 grid2(C_ * HW_ / 4 / 256, 1, NBL);   // (6300, 1, 20)
    apply_kernel<<<grid2, 256>>>(x, mask, out);
}

// round 3
// speedup vs baseline: 1.0463x; 1.0463x over previous
#include <cuda_runtime.h>
#include <stdint.h>

// Problem constants (fixed by the dataset)
#define B_  4
#define L_  5
#define C_  256
#define H_  100
#define W_  252
#define HW_ (H_ * W_)          // 25200
#define KSEL 1024
#define NBL (B_ * L_)          // 20
#define NWORDS 788             // ceil(25200/32)
#define NK 25                  // keys per thread (padded)

// Per-(b,l) pixel bitmask: bit = pixel survives top-K threshold.
__device__ uint32_t g_bitmask[NBL][800];

// Monotone map: float -> uint32 preserving order (ascending).
__device__ __forceinline__ uint32_t f2u(float f) {
    uint32_t u = __float_as_uint(f);
    return (u & 0x80000000u) ? ~u : (u | 0x80000000u);
}

// ---------------------------------------------------------------------------
// Kernel 1: per (b, l>0), exact K-th-largest radix select over
// d[hw] = max_c (psm[b,l,c,hw] - psm[b,0,c,hw]), then write pixel bitmask.
// One block per (b,l). Warp-aggregated histogram + parallel suffix-sum scan.
// ---------------------------------------------------------------------------
__global__ __launch_bounds__(1024, 1) void select_kernel(const float* __restrict__ psm) {
    const int blk = blockIdx.x;          // 0..15
    const int b = blk >> 2;
    const int l = 1 + (blk & 3);
    const int bl = b * L_ + l;

    const float* __restrict__ p_l = psm + (size_t)bl * 2 * HW_;
    const float* __restrict__ p_0 = psm + (size_t)(b * L_) * 2 * HW_;

    const int tid = threadIdx.x;

    // Uniform NK keys per thread; pad with 0 (minimal mapped value — can never
    // reach the K=1024-th-largest region, so it only inflates the lowest bins).
    uint32_t keys[NK];
    #pragma unroll
    for (int i = 0; i < NK; i++) {
        int hw = tid + i * 1024;
        if (hw < HW_) {
            float d0 = p_l[hw]       - p_0[hw];
            float d1 = p_l[HW_ + hw] - p_0[HW_ + hw];
            keys[i] = f2u(fmaxf(d0, d1));
        } else {
            keys[i] = 0u;
        }
    }

    __shared__ uint32_t hist[256];
    __shared__ uint32_t ssum[256];
    __shared__ uint32_t s_prefix, s_rem;
    if (tid == 0) { s_prefix = 0u; s_rem = KSEL; }
    __syncthreads();

    // 4 MSB-first radix passes (8 bits each) -> exact key of K-th largest.
    for (int shift = 24; shift >= 0; shift -= 8) {
        const uint32_t prefix = s_prefix;
        const uint32_t rem    = s_rem;
        if (tid < 256) hist[tid] = 0u;
        __syncthreads();

        const uint32_t pmask = (shift == 24) ? 0u : (0xFFFFFFFFu << (shift + 8));
        #pragma unroll
        for (int i = 0; i < NK; i++) {
            uint32_t k = keys[i];
            bool ok = ((k & pmask) == (prefix & pmask));
            unsigned m = __ballot_sync(0xFFFFFFFFu, ok);
            if (ok) {
                unsigned bin = (k >> shift) & 255u;
                unsigned peers = __match_any_sync(m, bin);
                if ((tid & 31) == (__ffs(peers) - 1))
                    atomicAdd(&hist[bin], __popc(peers));
            }
        }
        __syncthreads();

        // Inclusive suffix sum over bins (Hillis-Steele, 8 steps).
        if (tid < 256) ssum[tid] = hist[tid];
        __syncthreads();
        #pragma unroll
        for (int off = 1; off < 256; off <<= 1) {
            uint32_t v = 0;
            if (tid < 256) {
                v = ssum[tid];
                if (tid + off < 256) v += ssum[tid + off];
            }
            __syncthreads();
            if (tid < 256) ssum[tid] = v;
            __syncthreads();
        }

        // Threshold bin: largest d with suffix(d) >= rem. Exactly one hit.
        if (tid < 256) {
            bool hit = (ssum[tid] >= rem) && (tid == 255 || ssum[tid + 1] < rem);
            if (hit) {
                s_rem = rem - (ssum[tid] - hist[tid]);
                s_prefix = prefix | ((uint32_t)tid << shift);
            }
        }
        __syncthreads();
    }

    const uint32_t T = s_prefix;   // exact key of rank-K element

    // Build bitmask in shared, then flush to global.
    __shared__ uint32_t words[800];
    for (int w = tid; w < NWORDS; w += 1024) words[w] = 0u;
    __syncthreads();
    #pragma unroll
    for (int i = 0; i < NK; i++) {
        int hw = tid + i * 1024;
        if (hw < HW_ && keys[i] >= T)
            atomicOr(&words[hw >> 5], 1u << (hw & 31));
    }
    __syncthreads();
    for (int w = tid; w < NWORDS; w += 1024) g_bitmask[bl][w] = words[w];
}

// ---------------------------------------------------------------------------
// Kernel 2: stream x -> out. Pure bandwidth (at roofline per R2 ncu).
//   l==0              : copy
//   l>0 && mask==0    : write zeros (NO x read)
//   l>0 && mask!=0    : x * bit(pixel)
// One float4 per thread. grid = (6300, 1, 20), block = 256.
// ---------------------------------------------------------------------------
__global__ __launch_bounds__(256) void apply_kernel(const float* __restrict__ x,
                                                    const int* __restrict__ mask,
                                                    float* __restrict__ out) {
    const int bl = blockIdx.z;           // 0..19
    const int l = bl % L_;
    const size_t slice = (size_t)bl * (size_t)(C_ * HW_);
    const int idx4 = blockIdx.x * 256 + threadIdx.x;   // 0..1,612,799
    const size_t off = slice + (size_t)idx4 * 4;

    float4* __restrict__ o4 = reinterpret_cast<float4*>(out + off);

    if (l == 0) {
        *o4 = *reinterpret_cast<const float4*>(x + off);
        return;
    }
    if (mask[bl] == 0) {
        *o4 = make_float4(0.f, 0.f, 0.f, 0.f);
        return;
    }

    float4 v = *reinterpret_cast<const float4*>(x + off);
    // pixel index of first lane element within the (b,l) slice
    const int hw = (idx4 % (HW_ / 4)) * 4;     // HW_/4 = 6300; hw % 4 == 0
    const uint32_t wbits = g_bitmask[bl][hw >> 5] >> (hw & 31);
    v.x = (wbits & 1u) ? v.x : 0.f;
    v.y = (wbits & 2u) ? v.y : 0.f;
    v.z = (wbits & 4u) ? v.z : 0.f;
    v.w = (wbits & 8u) ? v.w : 0.f;
    *o4 = v;
}

extern "C" void kernel_launch(void* const* d_in, const int* in_sizes, int n_in,
                              void* d_out, int out_size) {
    const float* x   = (const float*)d_in[0];
    const float* psm = (const float*)d_in[1];
    const int*  mask = (const int*)d_in[2];
    float* out = (float*)d_out;

    select_kernel<<<B_ * (L_ - 1), 1024>>>(psm);

    dim3 grid2(C_ * HW_ / 4 / 256, 1, NBL);   // (6300, 1, 20)
    apply_kernel<<<grid2, 256>>>(x, mask, out);
}